// round 2
// baseline (speedup 1.0000x reference)
#include <cuda_runtime.h>
#include <cstdint>

#define B_  256
#define T_  2048
#define K2_ 52
#define PF  8   // emission prefetch depth (register pipeline)

// scratch (device globals: no allocations allowed)
__device__ float g_fw[B_];
__device__ float g_diff[B_];
__device__ int   g_len[B_];
__device__ int   g_i64;    // 1 if lengths/labels buffers are int64, 0 if int32

#define FFMA2(d,a,b,c) asm("fma.rn.f32x2 %0, %1, %2, %3;" : "=l"(d) : "l"(a), "l"(b), "l"(c))
#define FADD2(d,a,b)   asm("add.rn.f32x2 %0, %1, %2;"     : "=l"(d) : "l"(a), "l"(b))

// ---------------------------------------------------------------------------
// Prep: detect int32 vs int64 for lengths (values in [1,2048], never 0).
// If int64 (little-endian), every odd 32-bit word is the zero high-half.
// If int32, all 128 odd-index words are >= 1. Reads only the first 256 words,
// in-bounds for both layouts. Normalizes lengths into g_len.
// ---------------------------------------------------------------------------
__global__ void prep_kernel(const void* __restrict__ lens_raw)
{
    __shared__ int orred;
    const int tid = threadIdx.x;   // 0..255
    if (tid == 0) orred = 0;
    __syncthreads();
    const int* w = (const int*)lens_raw;
    const int v = w[tid];
    if (tid & 1) atomicOr(&orred, v);
    __syncthreads();
    const int is64 = (orred == 0) ? 1 : 0;
    g_len[tid] = is64 ? (int)(((const long long*)lens_raw)[tid]) : v;
    if (tid == 0) g_i64 = is64;
}

// ---------------------------------------------------------------------------
// Forward algorithm: one batch per 64-thread block. Thread s owns next-state s
// (s<52). M row (exp(trans[s][:])) lives in 26 packed f32x2 registers.
// p vector lives in shared (ping-pong). Per step:
//   q[s] = sum_prev M[s][prev] * v[prev]        (26 packed FMAs, broadcast LDS)
//   w[s] = q[s] * exp(em[b,t,s]) * 2^{-e}       (e = exponent of v[0], exact)
//   lz  += e                                    (exact integer bookkeeping)
// ---------------------------------------------------------------------------
__global__ __launch_bounds__(64, 8)
void fwd_kernel(const float* __restrict__ em,
                const float* __restrict__ tr)
{
    const int b = blockIdx.x;
    const int s = threadIdx.x;                  // 0..63
    const int srow = (s < K2_) ? s : (K2_ - 1); // clamp for idle lanes
    const int len = g_len[b];

    __shared__ __align__(16) float vb[2][56];   // ping-pong p buffers (52 used)
    __shared__ float red[64];

    // Build packed M row: m2[j] = (exp(tr[srow][2j]), exp(tr[srow][2j+1]))
    unsigned long long m2[26];
    {
        const float* row = tr + srow * K2_;
#pragma unroll
        for (int j = 0; j < 26; ++j) {
            float a = __expf(row[2 * j]);
            float c = __expf(row[2 * j + 1]);
            asm("mov.b64 %0, {%1, %2};" : "=l"(m2[j]) : "f"(a), "f"(c));
        }
    }

    // init p0 = one-hot on START tag (50)
    if (s < 56) vb[0][s] = (s == 50) ? 1.0f : 0.0f;

    // emission prefetch pipeline (raw values, exp'd at consume time)
    const float* eb = em + ((size_t)b * T_) * K2_ + srow;
    float eraw[PF];
#pragma unroll
    for (int i = 0; i < PF; ++i) {
        int idx = (i < len) ? i : (len - 1);
        eraw[i] = eb[(size_t)idx * K2_];
    }

    int lz = 0;      // sum of power-of-two exponents (exact)
    int p = 0;
    __syncthreads();

    for (int t = 0; t < len; ++t) {
        const float E = __expf(eraw[0]);        // MUFU, hidden under FMA chain
        const ulonglong2* V = reinterpret_cast<const ulonglong2*>(vb[p]);

        unsigned long long a0 = 0ULL, a1 = 0ULL, a2 = 0ULL, a3 = 0ULL;

        ulonglong2 v0v = V[0];
        // exact power-of-two renormalization factor from v[0]'s exponent
        unsigned int bits = (unsigned int)(v0v.x & 0xffffffffULL);
        int e = 0;
        if (bits) e = (int)((bits >> 23) & 0xff) - 127;
        if (e < -126) e = -126;
        if (e >  126) e =  126;
        const float r  = __uint_as_float((unsigned)(127 - e) << 23);
        const float rE = r * E;

        FFMA2(a0, m2[0], v0v.x, a0);
        FFMA2(a1, m2[1], v0v.y, a1);
#pragma unroll
        for (int j = 1; j < 13; ++j) {
            ulonglong2 vv = V[j];
            if (j & 1) {
                FFMA2(a2, m2[2 * j],     vv.x, a2);
                FFMA2(a3, m2[2 * j + 1], vv.y, a3);
            } else {
                FFMA2(a0, m2[2 * j],     vv.x, a0);
                FFMA2(a1, m2[2 * j + 1], vv.y, a1);
            }
        }
        FADD2(a0, a0, a2);
        FADD2(a1, a1, a3);
        FADD2(a0, a0, a1);
        const float qlo = __uint_as_float((unsigned)(a0 & 0xffffffffULL));
        const float qhi = __uint_as_float((unsigned)(a0 >> 32));
        const float w = (qlo + qhi) * rE;

        lz += e;
        if (s < K2_) vb[p ^ 1][s] = w;

        // rotate prefetch pipeline, issue next load (clamped index -> always valid)
#pragma unroll
        for (int i = 0; i < PF - 1; ++i) eraw[i] = eraw[i + 1];
        {
            int idx = t + PF;
            if (idx >= len) idx = len - 1;
            eraw[PF - 1] = eb[(size_t)idx * K2_];
        }

        __syncthreads();
        p ^= 1;
    }

    // terminal: fw = L + log( sum_s exp(trans[STOP][s]) * v[s] )
    float term = 0.0f;
    if (s < K2_) term = __expf(tr[(K2_ - 1) * K2_ + s]) * vb[p][s];
    red[s] = term;
    __syncthreads();
    if (s == 0) {
        float acc = 0.0f;
        for (int i = 0; i < K2_; ++i) acc += red[i];
        g_fw[b] = (float)((double)lz * 0.69314718055994530942) + __logf(acc);
    }
}

// ---------------------------------------------------------------------------
// Gold score: one batch per 256-thread block, strided gather + tree reduce.
// Handles int32 or int64 label storage via g_i64 flag (uniform branch).
// Writes diff[b] = forward[b] - gold[b].
// ---------------------------------------------------------------------------
__global__ void gold_kernel(const float* __restrict__ em,
                            const float* __restrict__ tr,
                            const void* __restrict__ labs_raw)
{
    const int b = blockIdx.x;
    const int tid = threadIdx.x;
    const int len = g_len[b];
    const int is64 = g_i64;
    const long long* lb64 = ((const long long*)labs_raw) + (size_t)b * T_;
    const int*       lb32 = ((const int*)labs_raw) + (size_t)b * T_;

    float acc = 0.0f;
    for (int t = tid; t < len; t += 256) {
        int lab  = is64 ? (int)lb64[t] : lb32[t];
        acc += em[((size_t)b * T_ + t) * K2_ + lab];
        int prev = (t == 0) ? (K2_ - 2)
                            : (is64 ? (int)lb64[t - 1] : lb32[t - 1]);
        acc += tr[lab * K2_ + prev];
    }

    __shared__ float sm[256];
    sm[tid] = acc;
    __syncthreads();
    for (int off = 128; off > 0; off >>= 1) {
        if (tid < off) sm[tid] += sm[tid + off];
        __syncthreads();
    }
    if (tid == 0) {
        int lastlab = is64 ? (int)lb64[len - 1] : lb32[len - 1];
        float gold = sm[0] + tr[(K2_ - 1) * K2_ + lastlab];
        g_diff[b] = g_fw[b] - gold;
    }
}

// ---------------------------------------------------------------------------
// Deterministic final mean over 256 batches.
// ---------------------------------------------------------------------------
__global__ void reduce_kernel(float* __restrict__ out)
{
    const int tid = threadIdx.x;
    __shared__ float sm[256];
    sm[tid] = g_diff[tid];
    __syncthreads();
    for (int off = 128; off > 0; off >>= 1) {
        if (tid < off) sm[tid] += sm[tid + off];
        __syncthreads();
    }
    if (tid == 0) out[0] = sm[0] * (1.0f / 256.0f);
}

extern "C" void kernel_launch(void* const* d_in, const int* in_sizes, int n_in,
                              void* d_out, int out_size)
{
    const float* em   = (const float*)d_in[0];   // [B, T, K2] f32
    const float* tr   = (const float*)d_in[1];   // [K2, K2]   f32
    const void*  lens = d_in[2];                 // [B]    i32 or i64
    const void*  labs = d_in[3];                 // [B, T] i32 or i64

    prep_kernel<<<1, 256>>>(lens);
    fwd_kernel<<<B_, 64>>>(em, tr);
    gold_kernel<<<B_, 256>>>(em, tr, labs);
    reduce_kernel<<<1, 256>>>((float*)d_out);
}

// round 5
// speedup vs baseline: 1.5755x; 1.5755x over previous
#include <cuda_runtime.h>
#include <cstdint>

#define B_  256
#define T_  2048
#define K2_ 52

// scratch (device globals: no allocations allowed)
__device__ float g_fw[B_];
__device__ float g_diff[B_];
__device__ int   g_len[B_];
__device__ int   g_ord[B_];
__device__ int   g_i64;    // 1 if lengths/labels buffers are int64, 0 if int32

#define FFMA2(d,a,b,c) asm("fma.rn.f32x2 %0, %1, %2, %3;" : "=l"(d) : "l"(a), "l"(b), "l"(c))
#define FADD2(d,a,b)   asm("add.rn.f32x2 %0, %1, %2;"     : "=l"(d) : "l"(a), "l"(b))

// ---------------------------------------------------------------------------
// Prep: detect int32 vs int64 for lengths (values in [1,2048], never 0).
// If int64 (LE), every odd 32-bit word is a zero high-half. Normalizes
// lengths into g_len and builds a longest-first permutation g_ord.
// ---------------------------------------------------------------------------
__global__ void prep_kernel(const void* __restrict__ lens_raw)
{
    __shared__ int orred;
    __shared__ int slen[B_];
    const int tid = threadIdx.x;   // 0..255
    if (tid == 0) orred = 0;
    __syncthreads();
    const int* w = (const int*)lens_raw;
    const int v = w[tid];
    if (tid & 1) atomicOr(&orred, v);
    __syncthreads();
    const int is64 = (orred == 0) ? 1 : 0;
    const int len = is64 ? (int)(((const long long*)lens_raw)[tid]) : v;
    g_len[tid] = len;
    slen[tid] = len;
    if (tid == 0) g_i64 = is64;
    __syncthreads();
    // longest-first rank (ties by index): deterministic permutation
    int rank = 0;
    for (int j = 0; j < B_; ++j) {
        int lj = slen[j];
        if (lj > len || (lj == len && j < tid)) ++rank;
    }
    g_ord[rank] = tid;
}

// ---------------------------------------------------------------------------
// Forward algorithm: one batch per 64-thread block. Thread s owns next-state
// s (s<52). M row (exp(trans[s][:])) in 26 packed f32x2 registers. p vector
// in shared ping-pong. Linear domain with exact power-of-two renorm every
// 2nd step (bounded ratio argument -> worst-case intermediate ~2^92: safe).
// Zero-guard on v[0]'s exponent (v[0]==0 at t=0: one-hot on START).
// Time loop unrolled x8 with a static 8-slot emission prefetch ring.
// ---------------------------------------------------------------------------
__global__ __launch_bounds__(64)
void fwd_kernel(const float* __restrict__ em,
                const float* __restrict__ tr)
{
    const int b = g_ord[blockIdx.x];
    const int s = threadIdx.x;                  // 0..63
    const int srow = (s < K2_) ? s : (K2_ - 1); // clamp for idle lanes
    const int len = g_len[b];

    __shared__ __align__(16) float vb[2][64];
    __shared__ float red[64];

    // Packed M row: m2[j] = (exp(tr[srow][2j]), exp(tr[srow][2j+1]))
    unsigned long long m2[26];
    {
        const float* row = tr + srow * K2_;
#pragma unroll
        for (int j = 0; j < 26; ++j) {
            float a = __expf(row[2 * j]);
            float c = __expf(row[2 * j + 1]);
            asm("mov.b64 %0, {%1, %2};" : "=l"(m2[j]) : "f"(a), "f"(c));
        }
    }

    // init p0 = one-hot on START tag (50)
    vb[0][s] = (s == 50) ? 1.0f : 0.0f;
    vb[1][s] = 0.0f;

    // emission prefetch ring (distance 8, static slots)
    const float* eb = em + ((size_t)b * T_) * K2_ + srow;
    float eraw[8];
#pragma unroll
    for (int i = 0; i < 8; ++i) {
        int idx = (i < len) ? i : (len - 1);
        eraw[i] = eb[(size_t)idx * K2_];
    }

    int lz = 0;      // sum of power-of-two exponents (exact)
    __syncthreads();

#define STEP(EI, SRC, DST, DOREN, TCUR) do {                                  \
    const float E_ = __expf(eraw[EI]);                                        \
    const ulonglong2* Vp_ = reinterpret_cast<const ulonglong2*>(vb[SRC]);     \
    ulonglong2 vv0_ = Vp_[0];                                                 \
    unsigned long long a0_=0ULL, a1_=0ULL, a2_=0ULL, a3_=0ULL;                \
    float scale_;                                                             \
    if (DOREN) {                                                              \
        unsigned bits_ = (unsigned)(vv0_.x & 0xffffffffULL);                  \
        int e_ = 0;                                                           \
        if (bits_) {                                                          \
            e_ = (int)((bits_ >> 23) & 0xff) - 127;                           \
            e_ = max(-126, min(126, e_));                                     \
        }                                                                     \
        lz += e_;                                                             \
        scale_ = __uint_as_float((unsigned)(127 - e_) << 23) * E_;            \
    } else {                                                                  \
        scale_ = E_;                                                          \
    }                                                                         \
    FFMA2(a0_, m2[0], vv0_.x, a0_);                                           \
    FFMA2(a1_, m2[1], vv0_.y, a1_);                                           \
    _Pragma("unroll")                                                         \
    for (int j_ = 1; j_ < 13; ++j_) {                                         \
        ulonglong2 vv_ = Vp_[j_];                                             \
        if (j_ & 1) { FFMA2(a2_, m2[2*j_], vv_.x, a2_);                       \
                      FFMA2(a3_, m2[2*j_+1], vv_.y, a3_); }                   \
        else        { FFMA2(a0_, m2[2*j_], vv_.x, a0_);                       \
                      FFMA2(a1_, m2[2*j_+1], vv_.y, a1_); }                   \
    }                                                                         \
    FADD2(a0_, a0_, a2_);                                                     \
    FADD2(a1_, a1_, a3_);                                                     \
    FADD2(a0_, a0_, a1_);                                                     \
    float qlo_ = __uint_as_float((unsigned)(a0_ & 0xffffffffULL));            \
    float qhi_ = __uint_as_float((unsigned)(a0_ >> 32));                      \
    if (s < K2_) vb[DST][s] = (qlo_ + qhi_) * scale_;                         \
    { int idx_ = (TCUR) + 8; idx_ = (idx_ > len - 1) ? (len - 1) : idx_;      \
      eraw[EI] = eb[(size_t)idx_ * K2_]; }                                    \
    __syncthreads();                                                          \
} while (0)

    int t = 0;
    const int nmain = len & ~7;
    for (; t < nmain; t += 8) {
        STEP(0, 0, 1, true,  t + 0);
        STEP(1, 1, 0, false, t + 1);
        STEP(2, 0, 1, true,  t + 2);
        STEP(3, 1, 0, false, t + 3);
        STEP(4, 0, 1, true,  t + 4);
        STEP(5, 1, 0, false, t + 5);
        STEP(6, 0, 1, true,  t + 6);
        STEP(7, 1, 0, false, t + 7);
    }
    // tail (0..7 steps), static ring slots since nmain % 8 == 0
    if (t < len) { STEP(0, 0, 1, true, t); ++t; }
    if (t < len) { STEP(1, 1, 0, true, t); ++t; }
    if (t < len) { STEP(2, 0, 1, true, t); ++t; }
    if (t < len) { STEP(3, 1, 0, true, t); ++t; }
    if (t < len) { STEP(4, 0, 1, true, t); ++t; }
    if (t < len) { STEP(5, 1, 0, true, t); ++t; }
    if (t < len) { STEP(6, 0, 1, true, t); ++t; }
#undef STEP

    // final state lives in vb[len & 1]
    const float* vf = vb[len & 1];

    // terminal: fw = lz*ln2 + log( sum_s exp(trans[STOP][s]) * v[s] )
    float term = 0.0f;
    if (s < K2_) term = __expf(tr[(K2_ - 1) * K2_ + s]) * vf[s];
    red[s] = term;
    __syncthreads();
    if (s == 0) {
        float acc = 0.0f;
        for (int i = 0; i < K2_; ++i) acc += red[i];
        g_fw[b] = (float)((double)lz * 0.69314718055994530942) + __logf(acc);
    }
}

// ---------------------------------------------------------------------------
// Gold score: one batch per 256-thread block, strided gather + tree reduce.
// Handles int32 or int64 label storage via g_i64 flag (uniform branch).
// Writes diff[b] = forward[b] - gold[b].
// ---------------------------------------------------------------------------
__global__ void gold_kernel(const float* __restrict__ em,
                            const float* __restrict__ tr,
                            const void* __restrict__ labs_raw)
{
    const int b = blockIdx.x;
    const int tid = threadIdx.x;
    const int len = g_len[b];
    const int is64 = g_i64;
    const long long* lb64 = ((const long long*)labs_raw) + (size_t)b * T_;
    const int*       lb32 = ((const int*)labs_raw) + (size_t)b * T_;

    float acc = 0.0f;
    for (int t = tid; t < len; t += 256) {
        int lab  = is64 ? (int)lb64[t] : lb32[t];
        acc += em[((size_t)b * T_ + t) * K2_ + lab];
        int prev = (t == 0) ? (K2_ - 2)
                            : (is64 ? (int)lb64[t - 1] : lb32[t - 1]);
        acc += tr[lab * K2_ + prev];
    }

    __shared__ float sm[256];
    sm[tid] = acc;
    __syncthreads();
    for (int off = 128; off > 0; off >>= 1) {
        if (tid < off) sm[tid] += sm[tid + off];
        __syncthreads();
    }
    if (tid == 0) {
        int lastlab = is64 ? (int)lb64[len - 1] : lb32[len - 1];
        float gold = sm[0] + tr[(K2_ - 1) * K2_ + lastlab];
        g_diff[b] = g_fw[b] - gold;
    }
}

// ---------------------------------------------------------------------------
// Deterministic final mean over 256 batches.
// ---------------------------------------------------------------------------
__global__ void reduce_kernel(float* __restrict__ out)
{
    const int tid = threadIdx.x;
    __shared__ float sm[256];
    sm[tid] = g_diff[tid];
    __syncthreads();
    for (int off = 128; off > 0; off >>= 1) {
        if (tid < off) sm[tid] += sm[tid + off];
        __syncthreads();
    }
    if (tid == 0) out[0] = sm[0] * (1.0f / 256.0f);
}

extern "C" void kernel_launch(void* const* d_in, const int* in_sizes, int n_in,
                              void* d_out, int out_size)
{
    const float* em   = (const float*)d_in[0];   // [B, T, K2] f32
    const float* tr   = (const float*)d_in[1];   // [K2, K2]   f32
    const void*  lens = d_in[2];                 // [B]    i32 or i64
    const void*  labs = d_in[3];                 // [B, T] i32 or i64

    prep_kernel<<<1, 256>>>(lens);
    fwd_kernel<<<B_, 64>>>(em, tr);
    gold_kernel<<<B_, 256>>>(em, tr, labs);
    reduce_kernel<<<1, 256>>>((float*)d_out);
}